// round 15
// baseline (speedup 1.0000x reference)
#include <cuda_runtime.h>
#include <cstdint>

// HGNN collapsed (graphs = contiguous 32-node blocks; batch = i // 32):
//   M[b,e,d] = (1/32) * sum_{i in graph b} H[i,e] * x[i,d]
//   P[b,e,f] = relu( sum_d M[b,e,d]*W[f,d] + bias[f] )   -> h_e (B*E, D)
//   c[b,f]   = (1/(32*48)) * sum_e s[b,e]*P[b,e,f]
// Output: c (B*D floats) ++ h_e (B*E*D floats).
// R6 measured latency-bound (occ 19%, issue 24%, grid=256). This version splits
// each graph over 4 e-quarter CTAs (grid 1024 x 128 thr). R9 failed (0.23) due
// to a missing graph offset in the H quarter load -- fixed here (b*NPG + i).

#define NV   8192
#define NE   48
#define ND   64
#define NB   256
#define NPG  32
#define NEQ  12    // edges per quarter-CTA
#define WPAD 132   // Wp row pitch (floats): N=4 bank floor for LDS.128

typedef unsigned long long u64;

__device__ float cscr[NB * 4][ND];   // c partials: [graph*4 + quarter][f]

__device__ __forceinline__ u64 pack2(float lo, float hi) {
    u64 r; asm("mov.b64 %0, {%1, %2};" : "=l"(r) : "f"(lo), "f"(hi)); return r;
}
__device__ __forceinline__ void unpack2(u64 v, float& lo, float& hi) {
    asm("mov.b64 {%0, %1}, %2;" : "=f"(lo), "=f"(hi) : "l"(v));
}
__device__ __forceinline__ u64 fma2(u64 a, u64 b, u64 c) {
    u64 d; asm("fma.rn.f32x2 %0, %1, %2, %3;" : "=l"(d) : "l"(a), "l"(b), "l"(c)); return d;
}
__device__ __forceinline__ void prefetch_l1(const void* p) {
    asm volatile("prefetch.global.L1 [%0];" :: "l"(p));
}

__global__ __launch_bounds__(128, 8)
void hgnn_main(const float* __restrict__ x, const float* __restrict__ H,
               const float* __restrict__ W, const float* __restrict__ bias,
               float* __restrict__ out) {
    __shared__ union {
        struct {
            float xs[NPG][ND];          // 8 KB : x rows of this graph
            float Hdup[NPG][NEQ * 2];   // 3 KB : this quarter's H as (h,h) pairs
        } p1;
        float Wp[32][WPAD];             // 16.9 KB : Wp[f2][2d+par] = W[2f2+par][d]
    } u;
    __shared__ float Mdup[NEQ][ND * 2]; // 6 KB : edge means as (m,m) pairs
    __shared__ float sedup[NEQ * 2];    // column sums as (s,s) pairs
    __shared__ float cpart[4][ND];      // 1 KB : c partials per e-group
    // total ~23.6 KB -> 8 CTAs/SM = 189 KB < 228 KB

    const int b   = blockIdx.x >> 2;    // graph (consecutive quarters share L2)
    const int q   = blockIdx.x & 3;     // e-quarter
    const int tid = threadIdx.x;
    const int f2  = tid & 31;           // feature-pair -> features {2f2, 2f2+1}
    const int eg  = tid >> 5;           // warp id 0..3, 3 local edges each
    const int e0  = eg * 3;             // local edge base (global: q*12 + e0)

    // warm W (16KB) + load bias pair (held in regs across phase 1)
    prefetch_l1((const char*)W + tid * 128);
    const float2 bb = __ldg((const float2*)bias + f2);

    // ---- cooperative loads ----
    {
        const float4* xg  = (const float4*)(x + (size_t)b * NPG * ND);
        float4*       xsd = (float4*)u.p1.xs;
        #pragma unroll
        for (int k = tid; k < NPG * ND / 4; k += 128) xsd[k] = xg[k];

        // H rows: 12-float segment of THIS GRAPH's node rows at column q*12
        // (48B offsets -> float4 aligned).  BUGFIX vs R9: include b*NPG.
        if (tid < NPG * 3) {
            int i = tid / 3, s = tid % 3;
            float4 h = *(const float4*)(H + ((size_t)(b * NPG + i)) * NE + q * NEQ + 4 * s);
            float4* Hd = (float4*)&u.p1.Hdup[i][8 * s];
            Hd[0] = make_float4(h.x, h.x, h.y, h.y);
            Hd[1] = make_float4(h.z, h.z, h.w, h.w);
        }
    }
    __syncthreads();

    // ---- column sums s[e] (duplicated pairs) ----
    if (tid < NEQ) {
        float s = 0.f;
        #pragma unroll
        for (int i = 0; i < NPG; i++) s += u.p1.Hdup[i][2 * tid];
        sedup[2 * tid]     = s;
        sedup[2 * tid + 1] = s;
    }

    // ---- phase 1: M[e][f-pair] = (1/32) sum_i H[i][e]*x[i][f-pair], 3 edges ----
    u64 acc0 = 0, acc1 = 0, acc2 = 0;
    #pragma unroll 4
    for (int i = 0; i < NPG; i++) {
        u64 xv = *(const u64*)&u.p1.xs[i][2 * f2];            // LDS.64
        const float* hrow = &u.p1.Hdup[i][6 * eg];            // 8B-aligned
        acc0 = fma2(*(const u64*)(hrow + 0), xv, acc0);       // broadcast LDS.64
        acc1 = fma2(*(const u64*)(hrow + 2), xv, acc1);
        acc2 = fma2(*(const u64*)(hrow + 4), xv, acc2);
    }
    {
        float lo, hi;
        unpack2(acc0, lo, hi);
        *(float4*)&Mdup[e0 + 0][4 * f2] = make_float4(lo * (1.f/NPG), lo * (1.f/NPG), hi * (1.f/NPG), hi * (1.f/NPG));
        unpack2(acc1, lo, hi);
        *(float4*)&Mdup[e0 + 1][4 * f2] = make_float4(lo * (1.f/NPG), lo * (1.f/NPG), hi * (1.f/NPG), hi * (1.f/NPG));
        unpack2(acc2, lo, hi);
        *(float4*)&Mdup[e0 + 2][4 * f2] = make_float4(lo * (1.f/NPG), lo * (1.f/NPG), hi * (1.f/NPG), hi * (1.f/NPG));
    }
    __syncthreads();   // phase-1 union buffers dead; Wp may overwrite

    // ---- stage W into smem pair layout (L1-hot, coalesced) ----
    {
        const float4* Wg = (const float4*)W;
        #pragma unroll
        for (int it = 0; it < 8; it++) {
            int k  = tid + 128 * it;       // float4 index 0..1023
            float4 w = Wg[k];
            int r  = k >> 4;               // W row 0..63
            int d0 = (k & 15) << 2;        // d base
            float* dst = &u.Wp[r >> 1][r & 1];
            dst[2 * (d0 + 0)] = w.x;
            dst[2 * (d0 + 1)] = w.y;
            dst[2 * (d0 + 2)] = w.z;
            dst[2 * (d0 + 3)] = w.w;
        }
    }
    __syncthreads();

    // ---- phase 2: P[e][f-pair] = relu(bias + sum_d M[e][d]*W[f][d]) ----
    const u64 b2 = pack2(bb.x, bb.y);
    u64 p0 = b2, p1 = b2, p2 = b2;

    const float* wp = &u.Wp[f2][0];
    #pragma unroll 4
    for (int d4 = 0; d4 < ND / 4; d4++) {
        ulonglong2 wv01 = *(const ulonglong2*)(wp + 8 * d4);      // LDS.128, N=4
        ulonglong2 wv23 = *(const ulonglong2*)(wp + 8 * d4 + 4);
        const int d = 4 * d4;
        {
            ulonglong2 m01 = *(const ulonglong2*)&Mdup[e0 + 0][2 * d];
            ulonglong2 m23 = *(const ulonglong2*)&Mdup[e0 + 0][2 * d + 4];
            p0 = fma2(m01.x, wv01.x, p0);
            p0 = fma2(m01.y, wv01.y, p0);
            p0 = fma2(m23.x, wv23.x, p0);
            p0 = fma2(m23.y, wv23.y, p0);
        }
        {
            ulonglong2 m01 = *(const ulonglong2*)&Mdup[e0 + 1][2 * d];
            ulonglong2 m23 = *(const ulonglong2*)&Mdup[e0 + 1][2 * d + 4];
            p1 = fma2(m01.x, wv01.x, p1);
            p1 = fma2(m01.y, wv01.y, p1);
            p1 = fma2(m23.x, wv23.x, p1);
            p1 = fma2(m23.y, wv23.y, p1);
        }
        {
            ulonglong2 m01 = *(const ulonglong2*)&Mdup[e0 + 2][2 * d];
            ulonglong2 m23 = *(const ulonglong2*)&Mdup[e0 + 2][2 * d + 4];
            p2 = fma2(m01.x, wv01.x, p2);
            p2 = fma2(m01.y, wv01.y, p2);
            p2 = fma2(m23.x, wv23.x, p2);
            p2 = fma2(m23.y, wv23.y, p2);
        }
    }

    // ---- epilogue: h_e store + c partial ----
    u64 cacc = 0ULL;
    float* he = out + NB * ND + ((size_t)b * NE + q * NEQ) * ND;
    u64 pv[3] = {p0, p1, p2};
    #pragma unroll
    for (int j = 0; j < 3; j++) {
        float lo, hi;
        unpack2(pv[j], lo, hi);
        lo = fmaxf(lo, 0.f);
        hi = fmaxf(hi, 0.f);
        *(float2*)&he[(size_t)(e0 + j) * ND + 2 * f2] = make_float2(lo, hi);
        cacc = fma2(pack2(lo, hi), *(const u64*)&sedup[2 * (e0 + j)], cacc);
    }
    {
        float clo, chi;
        unpack2(cacc, clo, chi);
        *(float2*)&cpart[eg][2 * f2] = make_float2(clo, chi);
    }
    __syncthreads();

    if (tid < ND) {
        cscr[blockIdx.x][tid] = cpart[0][tid] + cpart[1][tid]
                              + cpart[2][tid] + cpart[3][tid];
    }
}

// reduce the 4 quarter-partials per graph into c (deterministic order)
__global__ __launch_bounds__(256)
void hgnn_creduce(float* __restrict__ out) {
    int base = blockIdx.x * 512 + threadIdx.x;   // 2 elements per thread
    #pragma unroll
    for (int r = 0; r < 2; r++) {
        int i = base + 256 * r;                  // 0 .. B*D-1
        int b = i >> 6, f = i & 63;
        float c = __ldg(&cscr[4 * b + 0][f]) + __ldg(&cscr[4 * b + 1][f])
                + __ldg(&cscr[4 * b + 2][f]) + __ldg(&cscr[4 * b + 3][f]);
        out[i] = c * (1.0f / (NPG * NE));
    }
}

extern "C" void kernel_launch(void* const* d_in, const int* in_sizes, int n_in,
                              void* d_out, int out_size) {
    const float* x    = (const float*)d_in[0];   // (V, D)
    const float* H    = (const float*)d_in[1];   // (V, E)
    const float* W    = (const float*)d_in[2];   // (D, D)
    const float* bias = (const float*)d_in[3];   // (D,)
    float* out = (float*)d_out;                  // c (B*D) ++ h_e (B*E*D)

    hgnn_main<<<NB * 4, 128>>>(x, H, W, bias, out);
    hgnn_creduce<<<NB * ND / 512, 256>>>(out);
}

// round 16
// speedup vs baseline: 1.2569x; 1.2569x over previous
#include <cuda_runtime.h>
#include <cstdint>

// HGNN collapsed (graphs are contiguous 32-node blocks; batch = i // 32):
//   M[b,e,d] = (1/32) * sum_{i in graph b} H[i,e] * x[i,d]
//   P[b,e,f] = relu( sum_d M[b,e,d]*W[f,d] + bias[f] )      -> h_e (B*E, D)
//   c[b,f]   = (1/(32*48)) * sum_e s[b,e]*P[b,e,f],  s[b,e] = sum_{i in b} H[i,e]
// Output layout: c (B*D floats) followed by h_e (B*E*D floats).
// R6 (this structure, launch_bounds(256,2), 120 regs) measured 14.37us with
// occ 19.4% / issue 24.4% / nothing saturated. R15 showed (a) a second kernel
// costs ~4us fixed and (b) a 64-reg cap likely spilled. This round: single
// kernel, launch_bounds(256,3) (<=85 regs -> 3 CTA/SM, +50% warps), smaller
// unrolls to fit the reg budget without spills. Everything else identical.

#define NV   8192
#define NE   48
#define ND   64
#define NB   256
#define NPG  32
#define WPAD 132   // Wp row pitch in floats (128 + 4): N=4 bank floor for LDS.128

typedef unsigned long long u64;

__device__ __forceinline__ u64 pack2(float lo, float hi) {
    u64 r; asm("mov.b64 %0, {%1, %2};" : "=l"(r) : "f"(lo), "f"(hi)); return r;
}
__device__ __forceinline__ void unpack2(u64 v, float& lo, float& hi) {
    asm("mov.b64 {%0, %1}, %2;" : "=f"(lo), "=f"(hi) : "l"(v));
}
__device__ __forceinline__ u64 fma2(u64 a, u64 b, u64 c) {
    u64 d; asm("fma.rn.f32x2 %0, %1, %2, %3;" : "=l"(d) : "l"(a), "l"(b), "l"(c)); return d;
}
__device__ __forceinline__ void prefetch_l1(const void* p) {
    asm volatile("prefetch.global.L1 [%0];" :: "l"(p));
}

__global__ __launch_bounds__(256, 3)
void hgnn_kernel(const float* __restrict__ x, const float* __restrict__ H,
                 const float* __restrict__ W, const float* __restrict__ bias,
                 float* __restrict__ out) {
    // Phase-1 operands and the phase-2 W tile never live at the same time:
    __shared__ union {
        struct {
            float xs[NPG][ND];        //  8 KB : x rows of this graph
            float Hdup[NPG][NE * 2];  // 12 KB : H values as (h,h) pairs
        } p1;
        float Wp[32][WPAD];           // 16.9 KB : W pairs, Wp[f2][2d+par] = W[2f2+par][d]
    } u;                              // union: 20 KB
    __shared__ float Mdup[NE][ND * 2];   // 24 KB : edge means as (m,m) pairs
    __shared__ float sedup[NE * 2];      // column sums as (s,s) pairs
    __shared__ float cpart[8][ND];       //  2 KB : c partials per e-group
    // total static smem ~46.4 KB -> 3 CTAs/SM (139 KB < 228 KB)

    const int b   = blockIdx.x;
    const int tid = threadIdx.x;
    const int f2  = tid & 31;          // feature-pair id -> features {2f2, 2f2+1}
    const int eg  = tid >> 5;          // e-group 0..7 == warp id, 6 edges each
    const int e0  = eg * 6;

    // ---- warm all of W (16KB) + bias into L1: transpose later hits L1 ----
    prefetch_l1((const char*)W + tid * 64);   // 256 threads x 64B = 16KB
    const float2 bb = __ldg((const float2*)bias + f2);

    // ---- cooperative loads of x and H (vectorized, coalesced) ----
    {
        const float4* xg  = (const float4*)(x + (size_t)b * NPG * ND);
        float4*       xsd = (float4*)u.p1.xs;
        #pragma unroll
        for (int k = tid; k < NPG * ND / 4; k += 256) xsd[k] = xg[k];

        const float4* Hg = (const float4*)(H + (size_t)b * NPG * NE);
        float4*       Hd = (float4*)u.p1.Hdup;
        for (int k = tid; k < NPG * NE / 4; k += 256) {
            float4 h = Hg[k];
            Hd[2 * k]     = make_float4(h.x, h.x, h.y, h.y);
            Hd[2 * k + 1] = make_float4(h.z, h.z, h.w, h.w);
        }
    }
    __syncthreads();

    // ---- column sums s[e], duplicated (warps 0-1) ----
    if (tid < NE) {
        float s = 0.f;
        #pragma unroll
        for (int i = 0; i < NPG; i++) s += u.p1.Hdup[i][2 * tid];
        sedup[2 * tid]     = s;
        sedup[2 * tid + 1] = s;
    }

    // ---- phase 1: M[e][f-pair] = (1/32) sum_i H[i][e] * x[i][f-pair] ----
    u64 acc[6];
    #pragma unroll
    for (int j = 0; j < 6; j++) acc[j] = 0ULL;

    #pragma unroll 4
    for (int i = 0; i < NPG; i++) {
        u64 xv = *(const u64*)&u.p1.xs[i][2 * f2];                  // LDS.64, N=2
        #pragma unroll
        for (int j2 = 0; j2 < 3; j2++) {
            // one broadcast LDS.128 -> two ready-packed (h,h) operands
            ulonglong2 hv = *(const ulonglong2*)&u.p1.Hdup[i][2 * e0 + 4 * j2];
            acc[2 * j2]     = fma2(hv.x, xv, acc[2 * j2]);
            acc[2 * j2 + 1] = fma2(hv.y, xv, acc[2 * j2 + 1]);
        }
    }
    {
        const u64 sc = pack2(1.0f / NPG, 1.0f / NPG);
        #pragma unroll
        for (int j = 0; j < 6; j++) {
            float lo, hi;
            u64 m = fma2(acc[j], sc, 0ULL);                         // scale by 1/32
            unpack2(m, lo, hi);
            // store duplicated: Mdup[e][2f2]=(lo,lo), Mdup[e][2f2+1]=(hi,hi)
            *(float4*)&Mdup[e0 + j][4 * f2] = make_float4(lo, lo, hi, hi);
        }
    }
    __syncthreads();   // phase-1 smem dead; safe to overwrite union with Wp

    // ---- stage W into smem pair layout (coalesced L1-hot LDG.128) ----
    {
        const float4* Wg = (const float4*)W;
        #pragma unroll
        for (int it = 0; it < 4; it++) {
            int k  = tid + 256 * it;      // float4 index 0..1023
            float4 w = Wg[k];
            int r  = k >> 4;              // W row 0..63
            int d0 = (k & 15) << 2;       // d base 0,4,...,60
            float* dst = &u.Wp[r >> 1][r & 1];
            dst[2 * (d0 + 0)] = w.x;
            dst[2 * (d0 + 1)] = w.y;
            dst[2 * (d0 + 2)] = w.z;
            dst[2 * (d0 + 3)] = w.w;
        }
    }
    __syncthreads();

    // ---- phase 2: P[e][f-pair] = relu(bias + sum_d M[e][d] * W[f][d]) ----
    u64 pacc[6];
    {
        const u64 b2 = pack2(bb.x, bb.y);
        #pragma unroll
        for (int j = 0; j < 6; j++) pacc[j] = b2;
    }

    const float* wp = &u.Wp[f2][0];       // this thread's packed W pairs (512B)
    #pragma unroll 2
    for (int d4 = 0; d4 < ND / 4; d4++) {
        // pairs for d = 4*d4 .. 4*d4+3; each .x/.y is (W[2f2][d], W[2f2+1][d])
        ulonglong2 wv01 = *(const ulonglong2*)(wp + 8 * d4);        // LDS.128, N=4 floor
        ulonglong2 wv23 = *(const ulonglong2*)(wp + 8 * d4 + 4);
        const int d = 4 * d4;
        #pragma unroll
        for (int j = 0; j < 6; j++) {
            ulonglong2 m01 = *(const ulonglong2*)&Mdup[e0 + j][2 * d];     // broadcast
            ulonglong2 m23 = *(const ulonglong2*)&Mdup[e0 + j][2 * d + 4]; // broadcast
            pacc[j] = fma2(m01.x, wv01.x, pacc[j]);
            pacc[j] = fma2(m01.y, wv01.y, pacc[j]);
            pacc[j] = fma2(m23.x, wv23.x, pacc[j]);
            pacc[j] = fma2(m23.y, wv23.y, pacc[j]);
        }
    }

    // ---- epilogue: h_e store + packed c accumulation ----
    u64 cacc = 0ULL;
    float* he = out + NB * ND + (size_t)b * NE * ND;
    #pragma unroll
    for (int j = 0; j < 6; j++) {
        float lo, hi;
        unpack2(pacc[j], lo, hi);
        lo = fmaxf(lo, 0.f);
        hi = fmaxf(hi, 0.f);
        *(float2*)&he[(size_t)(e0 + j) * ND + 2 * f2] = make_float2(lo, hi); // coalesced STG.64
        cacc = fma2(pack2(lo, hi), *(const u64*)&sedup[2 * (e0 + j)], cacc);
    }
    {
        float clo, chi;
        unpack2(cacc, clo, chi);
        *(float2*)&cpart[eg][2 * f2] = make_float2(clo, chi);
    }
    __syncthreads();

    if (tid < ND) {
        float c = 0.f;
        #pragma unroll
        for (int g = 0; g < 8; g++) c += cpart[g][tid];
        out[b * ND + tid] = c * (1.0f / (NPG * NE));
    }
}

extern "C" void kernel_launch(void* const* d_in, const int* in_sizes, int n_in,
                              void* d_out, int out_size) {
    const float* x    = (const float*)d_in[0];   // (V, D)
    const float* H    = (const float*)d_in[1];   // (V, E)
    const float* W    = (const float*)d_in[2];   // (D, D)
    const float* bias = (const float*)d_in[3];   // (D,)
    float* out = (float*)d_out;                  // c (B*D) ++ h_e (B*E*D)

    hgnn_kernel<<<NB, 256>>>(x, H, W, bias, out);
}